// round 4
// baseline (speedup 1.0000x reference)
#include <cuda_runtime.h>
#include <cuda_bf16.h>
#include <cstdint>
#include <math.h>

#define B_  8192
#define H_  1024
#define HH_ 512
#define M_  16
#define BM  128
#define BN  128
#define NTH 128
#define MARGIN_THRESH 0.03f

typedef __nv_bfloat16 bf16;

// ---------------- scratch (device globals, no allocation) ----------------
__device__ bf16  g_qhi[B_ * H_];
__device__ bf16  g_qlo[B_ * H_];
__device__ bf16  g_w1hi[HH_ * H_];
__device__ bf16  g_w1lo[HH_ * H_];
__device__ bf16  g_ew1b[M_ * HH_ * H_];
__device__ bf16  g_ew2b[M_ * H_ * HH_];
__device__ float g_X1[B_ * HH_];
__device__ bf16  g_Hb[B_ * HH_];
__device__ float g_Obuf[B_ * H_];
__device__ int   g_top[B_];
__device__ int   g_rows[M_ * B_];
__device__ int   g_cnt[M_];
__device__ int   g_flag[B_];
__device__ int   g_nflag;

// ---------------- PTX helpers ----------------
__device__ __forceinline__ uint32_t smem_u32(const void* p) {
    uint32_t a;
    asm("{ .reg .u64 t; cvta.to.shared.u64 t, %1; cvt.u32.u64 %0, t; }" : "=r"(a) : "l"(p));
    return a;
}
__device__ __forceinline__ void cp16(uint32_t dst, const void* src) {
    asm volatile("cp.async.cg.shared.global [%0], [%1], 16;" :: "r"(dst), "l"(src));
}
__device__ __forceinline__ void cp_commit() { asm volatile("cp.async.commit_group;" ::: "memory"); }
template <int N> __device__ __forceinline__ void cp_wait() {
    asm volatile("cp.async.wait_group %0;" :: "n"(N) : "memory");
}
__device__ __forceinline__ void ldmx4(uint32_t* r, uint32_t addr) {
    asm volatile("ldmatrix.sync.aligned.m8n8.x4.shared.b16 {%0,%1,%2,%3}, [%4];"
                 : "=r"(r[0]), "=r"(r[1]), "=r"(r[2]), "=r"(r[3]) : "r"(addr));
}
__device__ __forceinline__ void mma16816(float* d, const uint32_t* a, const uint32_t* b) {
    asm volatile(
        "mma.sync.aligned.m16n8k16.row.col.f32.bf16.bf16.f32 "
        "{%0,%1,%2,%3}, {%4,%5,%6,%7}, {%8,%9}, {%0,%1,%2,%3};"
        : "+f"(d[0]), "+f"(d[1]), "+f"(d[2]), "+f"(d[3])
        : "r"(a[0]), "r"(a[1]), "r"(a[2]), "r"(a[3]), "r"(b[0]), "r"(b[1]));
}

// ---------------- conversion kernels (8 elems / thread, 16B stores) -------
__global__ void split8_k(const float* __restrict__ x, bf16* __restrict__ hi,
                         bf16* __restrict__ lo, int n) {
    int i = (blockIdx.x * blockDim.x + threadIdx.x) * 8;
    if (i >= n) return;
    float4 v0 = *(const float4*)(x + i);
    float4 v1 = *(const float4*)(x + i + 4);
    float vv[8] = {v0.x, v0.y, v0.z, v0.w, v1.x, v1.y, v1.z, v1.w};
    __nv_bfloat162 hp[4], lp[4];
#pragma unroll
    for (int j = 0; j < 4; j++) {
        bf16 h0 = __float2bfloat16_rn(vv[2*j]);
        bf16 h1 = __float2bfloat16_rn(vv[2*j+1]);
        hp[j] = __nv_bfloat162(h0, h1);
        lp[j] = __nv_bfloat162(__float2bfloat16_rn(vv[2*j]   - __bfloat162float(h0)),
                               __float2bfloat16_rn(vv[2*j+1] - __bfloat162float(h1)));
    }
    *(uint4*)(hi + i) = *(uint4*)hp;
    *(uint4*)(lo + i) = *(uint4*)lp;
}

__global__ void cvt8_k(const float* __restrict__ x, bf16* __restrict__ y, int n) {
    int i = (blockIdx.x * blockDim.x + threadIdx.x) * 8;
    if (i >= n) return;
    float4 v0 = *(const float4*)(x + i);
    float4 v1 = *(const float4*)(x + i + 4);
    __nv_bfloat162 p[4];
    p[0] = __nv_bfloat162(__float2bfloat16_rn(v0.x), __float2bfloat16_rn(v0.y));
    p[1] = __nv_bfloat162(__float2bfloat16_rn(v0.z), __float2bfloat16_rn(v0.w));
    p[2] = __nv_bfloat162(__float2bfloat16_rn(v1.x), __float2bfloat16_rn(v1.y));
    p[3] = __nv_bfloat162(__float2bfloat16_rn(v1.z), __float2bfloat16_rn(v1.w));
    *(uint4*)(y + i) = *(uint4*)p;
}

// ---------------- HMMA GEMM: C[i,n] = act(sum_k A[i,k]*W[n,k] + b[n]) ----
// SPLIT: 3-pass hi/lo bf16 (near-fp32).
// GROUPED: 0 = plain rows, 1 = per-expert rows (g_rows/g_cnt, blockIdx.z),
//          2 = flagged rows (g_flag/g_nflag).
// Tiles: CTA 128x128, 4 warps of 64x64, K-chunk 64, cp.async double buffer.
template <int SPLIT, int GROUPED, int RELU, typename OutT>
__global__ __launch_bounds__(NTH, 2)
void gemm_mma(const bf16* __restrict__ Ahi, const bf16* __restrict__ Alo,
              const bf16* __restrict__ Whi, const bf16* __restrict__ Wlo,
              const float* __restrict__ bias, OutT* __restrict__ C,
              int N, int K, int plain_rows)
{
    int e = (GROUPED == 1) ? blockIdx.z : 0;
    int nrows = (GROUPED == 1) ? g_cnt[e] : (GROUPED == 2) ? g_nflag : plain_rows;
    int row0 = blockIdx.x * BM;
    if (row0 >= nrows) return;
    int col0 = blockIdx.y * BN;

    const bf16*  Wh = Whi + ((GROUPED == 1) ? (size_t)e * N * K : 0);
    const bf16*  Wl = Wlo + ((GROUPED == 1) ? (size_t)e * N * K : 0);
    const float* bp = bias + ((GROUPED == 1) ? (size_t)e * N : 0);

    extern __shared__ char smem[];
    int*   srow  = (int*)smem;            // [128]
    float* sbias = (float*)(smem + 512);  // [128]
    constexpr int HDR   = 1024;
    constexpr int TILE  = BM * 128;       // 16KB: 128 rows x 128B
    constexpr int STAGE = (1 + SPLIT) * 2 * TILE;
    constexpr int AHI = 0, ALO = TILE, WHI = (1 + SPLIT) * TILE, WLO = WHI + TILE;

    int t = threadIdx.x;
    {
        int gr = row0 + t;
        int cr = gr < nrows ? gr : nrows - 1;
        srow[t] = (GROUPED == 1) ? g_rows[e * B_ + cr]
                : (GROUPED == 2) ? g_flag[cr] : cr;
        sbias[t] = bp[col0 + t];
    }
    __syncthreads();

    uint32_t sb = smem_u32(smem) + HDR;

    // loader: thread t loads A row t and W row t (8 x 16B each, swizzled)
    const int tx7 = t & 7;
    const size_t arow = (size_t)srow[t] * K;
    const size_t wrow = (size_t)(col0 + t) * K;

    auto issue = [&](int c) {
        uint32_t st = sb + (c & 1) * STAGE;
        size_t koff = (size_t)c * 64;
#pragma unroll
        for (int j = 0; j < 8; j++) {
            uint32_t doff = t * 128 + ((j ^ tx7) * 16);
            cp16(st + AHI + doff, Ahi + arow + koff + j * 8);
            cp16(st + WHI + doff, Wh  + wrow + koff + j * 8);
            if (SPLIT) {
                cp16(st + ALO + doff, Alo + arow + koff + j * 8);
                cp16(st + WLO + doff, Wl  + wrow + koff + j * 8);
            }
        }
        cp_commit();
    };

    const int nc = K >> 6;
    issue(0);
    issue(1);
    cp_wait<1>();
    __syncthreads();

    const int wid = t >> 5, lane = t & 31;
    const int wm = (wid & 1) * 64;   // warp row offset
    const int wn = (wid >> 1) * 64;  // warp col offset
    const int rb = lane & 15, csel = lane >> 4, x7 = rb & 7;

    float acc[4][8][4];
#pragma unroll
    for (int i = 0; i < 4; i++)
#pragma unroll
        for (int j = 0; j < 8; j++)
#pragma unroll
            for (int q = 0; q < 4; q++) acc[i][j][q] = 0.0f;

    uint32_t arow_b[4], wrow_b[4];
#pragma unroll
    for (int mi = 0; mi < 4; mi++) arow_b[mi] = (wm + mi * 16 + rb) * 128;
#pragma unroll
    for (int nb = 0; nb < 4; nb++) wrow_b[nb] = (wn + nb * 16 + rb) * 128;

    for (int c = 0; c < nc; c++) {
        uint32_t st = sb + (c & 1) * STAGE;
#pragma unroll
        for (int ks = 0; ks < 4; ks++) {
            uint32_t ksel = ((2 * ks + csel) ^ x7) * 16;
            uint32_t ah[4][4], bh[8][2];
#pragma unroll
            for (int mi = 0; mi < 4; mi++)
                ldmx4(ah[mi], st + AHI + arow_b[mi] + ksel);
#pragma unroll
            for (int nb = 0; nb < 4; nb++) {
                uint32_t r[4];
                ldmx4(r, st + WHI + wrow_b[nb] + ksel);
                bh[2 * nb][0] = r[0]; bh[2 * nb + 1][0] = r[1];
                bh[2 * nb][1] = r[2]; bh[2 * nb + 1][1] = r[3];
            }
#pragma unroll
            for (int mi = 0; mi < 4; mi++)
#pragma unroll
                for (int ni = 0; ni < 8; ni++)
                    mma16816(acc[mi][ni], ah[mi], bh[ni]);
            if (SPLIT) {
                uint32_t al[4][4], bl[8][2];
#pragma unroll
                for (int mi = 0; mi < 4; mi++)
                    ldmx4(al[mi], st + ALO + arow_b[mi] + ksel);
#pragma unroll
                for (int nb = 0; nb < 4; nb++) {
                    uint32_t r[4];
                    ldmx4(r, st + WLO + wrow_b[nb] + ksel);
                    bl[2 * nb][0] = r[0]; bl[2 * nb + 1][0] = r[1];
                    bl[2 * nb][1] = r[2]; bl[2 * nb + 1][1] = r[3];
                }
#pragma unroll
                for (int mi = 0; mi < 4; mi++)
#pragma unroll
                    for (int ni = 0; ni < 8; ni++) {
                        mma16816(acc[mi][ni], ah[mi], bl[ni]);
                        mma16816(acc[mi][ni], al[mi], bh[ni]);
                    }
            }
        }
        __syncthreads();
        if (c + 2 < nc) issue(c + 2);
        else            cp_commit();
        cp_wait<1>();
        __syncthreads();
    }

    // epilogue
    const int lr4 = lane >> 2, lc2 = 2 * (lane & 3);
#pragma unroll
    for (int mi = 0; mi < 4; mi++) {
        int r0i = wm + mi * 16 + lr4;
        int r1i = r0i + 8;
        bool v0 = (row0 + r0i) < nrows;
        bool v1 = (row0 + r1i) < nrows;
        size_t g0 = (size_t)srow[r0i] * N + col0;
        size_t g1 = (size_t)srow[r1i] * N + col0;
#pragma unroll
        for (int ni = 0; ni < 8; ni++) {
            int cc = wn + ni * 8 + lc2;
            float ba = sbias[cc], bb = sbias[cc + 1];
            float x0 = acc[mi][ni][0] + ba, x1 = acc[mi][ni][1] + bb;
            float y0 = acc[mi][ni][2] + ba, y1 = acc[mi][ni][3] + bb;
            if (RELU) {
                x0 = fmaxf(x0, 0.0f); x1 = fmaxf(x1, 0.0f);
                y0 = fmaxf(y0, 0.0f); y1 = fmaxf(y1, 0.0f);
            }
            if (sizeof(OutT) == 4) {
                if (v0) *(float2*)((float*)C + g0 + cc) = make_float2(x0, x1);
                if (v1) *(float2*)((float*)C + g1 + cc) = make_float2(y0, y1);
            } else {
                uint32_t p0, p1;
                asm("cvt.rn.bf16x2.f32 %0, %1, %2;" : "=r"(p0) : "f"(x1), "f"(x0));
                asm("cvt.rn.bf16x2.f32 %0, %1, %2;" : "=r"(p1) : "f"(y1), "f"(y0));
                if (v0) *(uint32_t*)((bf16*)C + g0 + cc) = p0;
                if (v1) *(uint32_t*)((bf16*)C + g1 + cc) = p1;
            }
        }
    }
}

// --------- logits + argmax with margin flagging -------------------------
__global__ void logits_argmax_kernel(const float* __restrict__ W3,
                                     const float* __restrict__ b3)
{
    __shared__ float sW[M_ * HH_];
    __shared__ float sb[M_];
    for (int i = threadIdx.x; i < M_ * HH_; i += blockDim.x) sW[i] = W3[i];
    if (threadIdx.x < M_) sb[threadIdx.x] = b3[threadIdx.x];
    __syncthreads();

    int gw   = (blockIdx.x * blockDim.x + threadIdx.x) >> 5;
    int lane = threadIdx.x & 31;
    int nw   = (gridDim.x * blockDim.x) >> 5;

    for (int row = gw; row < B_; row += nw) {
        const float* x = g_X1 + (size_t)row * HH_;
        float xv[16];
#pragma unroll
        for (int tt = 0; tt < 16; tt++) xv[tt] = x[lane + 32 * tt];
        float best = -3.0e38f, second = -3.0e38f;
        int   bi   = 0;
#pragma unroll
        for (int m = 0; m < M_; m++) {
            float p = 0.0f;
            const float* wrow = sW + m * HH_;
#pragma unroll
            for (int tt = 0; tt < 16; tt++)
                p = fmaf(xv[tt], wrow[lane + 32 * tt], p);
#pragma unroll
            for (int o = 16; o; o >>= 1) p += __shfl_xor_sync(0xffffffffu, p, o);
            p += sb[m];
            if (p > best) { second = best; best = p; bi = m; }
            else if (p > second) second = p;
        }
        if (lane == 0) {
            g_top[row] = bi;
            if (best - second < MARGIN_THRESH) {
                int fp = atomicAdd(&g_nflag, 1);
                g_flag[fp] = row;
            }
        }
    }
}

// --------- fix argmax for flagged rows (their X1 is now exact) ----------
__global__ void logits_fix_kernel(const float* __restrict__ W3,
                                  const float* __restrict__ b3)
{
    __shared__ float sW[M_ * HH_];
    __shared__ float sb[M_];
    for (int i = threadIdx.x; i < M_ * HH_; i += blockDim.x) sW[i] = W3[i];
    if (threadIdx.x < M_) sb[threadIdx.x] = b3[threadIdx.x];
    __syncthreads();

    int gw   = (blockIdx.x * blockDim.x + threadIdx.x) >> 5;
    int lane = threadIdx.x & 31;
    int nw   = (gridDim.x * blockDim.x) >> 5;
    int nf   = g_nflag;

    for (int idx = gw; idx < nf; idx += nw) {
        int row = g_flag[idx];
        const float* x = g_X1 + (size_t)row * HH_;
        float xv[16];
#pragma unroll
        for (int tt = 0; tt < 16; tt++) xv[tt] = x[lane + 32 * tt];
        float best = -3.0e38f;
        int   bi   = 0;
#pragma unroll
        for (int m = 0; m < M_; m++) {
            float p = 0.0f;
            const float* wrow = sW + m * HH_;
#pragma unroll
            for (int tt = 0; tt < 16; tt++)
                p = fmaf(xv[tt], wrow[lane + 32 * tt], p);
#pragma unroll
            for (int o = 16; o; o >>= 1) p += __shfl_xor_sync(0xffffffffu, p, o);
            p += sb[m];
            if (p > best) { best = p; bi = m; }
        }
        if (lane == 0) g_top[row] = bi;
    }
}

__global__ void zero_kernel() {
    if (threadIdx.x < M_) g_cnt[threadIdx.x] = 0;
    if (threadIdx.x == M_) g_nflag = 0;
}

__global__ void scatter_kernel() {
    int b = blockIdx.x * blockDim.x + threadIdx.x;
    if (b < B_) {
        int m = g_top[b];
        int p = atomicAdd(&g_cnt[m], 1);
        g_rows[m * B_ + p] = b;
    }
}

// normalize(g*v) == v / max(||v||,eps) for gate g > 0 (top-1 prob >= 1/16)
__global__ void finalize_kernel(const float* __restrict__ Q, float* __restrict__ out)
{
    int row = blockIdx.x;
    const float* o = g_Obuf + (size_t)row * H_;
    float s = 0.0f;
    for (int i = threadIdx.x; i < H_; i += 256) { float v = o[i]; s = fmaf(v, v, s); }
#pragma unroll
    for (int off = 16; off; off >>= 1) s += __shfl_xor_sync(0xffffffffu, s, off);
    __shared__ float red[8];
    if ((threadIdx.x & 31) == 0) red[threadIdx.x >> 5] = s;
    __syncthreads();
    float tot = 0.0f;
#pragma unroll
    for (int w = 0; w < 8; w++) tot += red[w];
    float inv = 1.0f / fmaxf(sqrtf(tot), 1e-6f);

    const float* qr = Q + (size_t)row * H_;
    float* orow = out + (size_t)row * H_;
    for (int i = threadIdx.x; i < H_; i += 256)
        orow[i] = fmaf(o[i], inv, qr[i]);
}

// ---------------- launch ----------------
extern "C" void kernel_launch(void* const* d_in, const int* in_sizes, int n_in,
                              void* d_out, int out_size)
{
    const float* q   = (const float*)d_in[0];
    const float* c1w = (const float*)d_in[1];
    const float* c1b = (const float*)d_in[2];
    const float* c3w = (const float*)d_in[3];
    const float* c3b = (const float*)d_in[4];
    const float* ew1 = (const float*)d_in[5];
    const float* eb1 = (const float*)d_in[6];
    const float* ew2 = (const float*)d_in[7];
    const float* eb2 = (const float*)d_in[8];
    float* out = (float*)d_out;

    void *pqh, *pql, *pw1h, *pw1l, *pe1, *pe2, *pX1, *pHb, *pO;
    cudaGetSymbolAddress(&pqh,  g_qhi);
    cudaGetSymbolAddress(&pql,  g_qlo);
    cudaGetSymbolAddress(&pw1h, g_w1hi);
    cudaGetSymbolAddress(&pw1l, g_w1lo);
    cudaGetSymbolAddress(&pe1,  g_ew1b);
    cudaGetSymbolAddress(&pe2,  g_ew2b);
    cudaGetSymbolAddress(&pX1,  g_X1);
    cudaGetSymbolAddress(&pHb,  g_Hb);
    cudaGetSymbolAddress(&pO,   g_Obuf);

    // conversions (q and w1 split hi/lo for the exact-fallback path)
    split8_k<<<B_ * H_ / 8 / 256, 256>>>(q, (bf16*)pqh, (bf16*)pql, B_ * H_);
    split8_k<<<HH_ * H_ / 8 / 256, 256>>>(c1w, (bf16*)pw1h, (bf16*)pw1l, HH_ * H_);
    cvt8_k<<<M_ * HH_ * H_ / 8 / 256, 256>>>(ew1, (bf16*)pe1, M_ * HH_ * H_);
    cvt8_k<<<M_ * H_ * HH_ / 8 / 256, 256>>>(ew2, (bf16*)pe2, M_ * H_ * HH_);

    constexpr int SMEM_STD   = 1024 + 2 * 2 * BM * 128;  // 66560
    constexpr int SMEM_SPLIT = 1024 + 2 * 4 * BM * 128;  // 132096

    cudaFuncSetAttribute(gemm_mma<0, 0, 1, float>,
                         cudaFuncAttributeMaxDynamicSharedMemorySize, SMEM_STD);
    cudaFuncSetAttribute(gemm_mma<1, 2, 1, float>,
                         cudaFuncAttributeMaxDynamicSharedMemorySize, SMEM_SPLIT);
    cudaFuncSetAttribute(gemm_mma<0, 1, 1, bf16>,
                         cudaFuncAttributeMaxDynamicSharedMemorySize, SMEM_STD);
    cudaFuncSetAttribute(gemm_mma<0, 1, 0, float>,
                         cudaFuncAttributeMaxDynamicSharedMemorySize, SMEM_STD);

    // 1) gating hidden, single-pass bf16: X1 = relu(Q @ c1w^T + b)
    gemm_mma<0, 0, 1, float><<<dim3(B_ / BM, HH_ / BN, 1), NTH, SMEM_STD>>>(
        (const bf16*)pqh, nullptr, (const bf16*)pw1h, nullptr,
        c1b, (float*)pX1, HH_, H_, B_);

    // 2) zero counters, then logits + argmax with margin flagging
    zero_kernel<<<1, 32>>>();
    logits_argmax_kernel<<<64, 256>>>(c3w, c3b);

    // 3) exact (split 3-pass) X1 recompute for flagged rows only
    gemm_mma<1, 2, 1, float><<<dim3(B_ / BM, HH_ / BN, 1), NTH, SMEM_SPLIT>>>(
        (const bf16*)pqh, (const bf16*)pql, (const bf16*)pw1h, (const bf16*)pw1l,
        c1b, (float*)pX1, HH_, H_, 0);
    logits_fix_kernel<<<32, 256>>>(c3w, c3b);

    // 4) bucket rows by expert
    scatter_kernel<<<B_ / 256, 256>>>();

    // 5) expert hidden: H = relu(Qg @ ew1[m]^T + b1[m])  (bf16 out)
    gemm_mma<0, 1, 1, bf16><<<dim3(B_ / BM, HH_ / BN, M_), NTH, SMEM_STD>>>(
        (const bf16*)pqh, nullptr, (const bf16*)pe1, nullptr,
        eb1, (bf16*)pHb, HH_, H_, 0);

    // 6) expert out: O = Hg @ ew2[m]^T + b2[m]  (fp32 out)
    gemm_mma<0, 1, 0, float><<<dim3(B_ / BM, H_ / BN, M_), NTH, SMEM_STD>>>(
        (const bf16*)pHb, nullptr, (const bf16*)pe2, nullptr,
        eb2, (float*)pO, H_, HH_, 0);

    // 7) out = normalize(O) + Q
    finalize_kernel<<<B_, 256>>>(q, out);
}

// round 5
// speedup vs baseline: 1.1908x; 1.1908x over previous
#include <cuda_runtime.h>
#include <cuda_bf16.h>
#include <cstdint>
#include <math.h>

#define B_  8192
#define H_  1024
#define HH_ 512
#define M_  16
#define BM  128
#define BN  128
#define NTH 256
#define MARGIN_THRESH 0.03f

typedef __nv_bfloat16 bf16;

// ---------------- scratch (device globals, no allocation) ----------------
__device__ bf16  g_qhi[B_ * H_];
__device__ bf16  g_qlo[B_ * H_];
__device__ bf16  g_w1hi[HH_ * H_];
__device__ bf16  g_w1lo[HH_ * H_];
__device__ bf16  g_ew1b[M_ * HH_ * H_];
__device__ bf16  g_ew2b[M_ * H_ * HH_];
__device__ float g_X1[B_ * HH_];
__device__ bf16  g_Hb[B_ * HH_];
__device__ float g_Obuf[B_ * H_];
__device__ int   g_top[B_];
__device__ int   g_rows[M_ * B_];
__device__ int   g_cnt[M_];
__device__ int   g_flag[B_];
__device__ int   g_nflag;

// ---------------- PTX helpers (all sm_80-compatible) ----------------
__device__ __forceinline__ uint32_t smem_u32(const void* p) {
    uint32_t a;
    asm("{ .reg .u64 t; cvta.to.shared.u64 t, %1; cvt.u32.u64 %0, t; }" : "=r"(a) : "l"(p));
    return a;
}
__device__ __forceinline__ void cp16(uint32_t dst, const void* src) {
    asm volatile("cp.async.cg.shared.global [%0], [%1], 16;" :: "r"(dst), "l"(src));
}
__device__ __forceinline__ void cp_commit() { asm volatile("cp.async.commit_group;" ::: "memory"); }
template <int N> __device__ __forceinline__ void cp_wait() {
    asm volatile("cp.async.wait_group %0;" :: "n"(N) : "memory");
}
__device__ __forceinline__ void ldmx4(uint32_t* r, uint32_t addr) {
    asm volatile("ldmatrix.sync.aligned.m8n8.x4.shared.b16 {%0,%1,%2,%3}, [%4];"
                 : "=r"(r[0]), "=r"(r[1]), "=r"(r[2]), "=r"(r[3]) : "r"(addr));
}
__device__ __forceinline__ void mma16816(float* d, const uint32_t* a, const uint32_t* b) {
    asm volatile(
        "mma.sync.aligned.m16n8k16.row.col.f32.bf16.bf16.f32 "
        "{%0,%1,%2,%3}, {%4,%5,%6,%7}, {%8,%9}, {%0,%1,%2,%3};"
        : "+f"(d[0]), "+f"(d[1]), "+f"(d[2]), "+f"(d[3])
        : "r"(a[0]), "r"(a[1]), "r"(a[2]), "r"(a[3]), "r"(b[0]), "r"(b[1]));
}

// ---------------- conversion kernels (16 elems / thread) -------
__global__ void split16_k(const float* __restrict__ x, bf16* __restrict__ hi,
                          bf16* __restrict__ lo, int n) {
    int i = (blockIdx.x * blockDim.x + threadIdx.x) * 16;
    if (i >= n) return;
    float4 v[4];
#pragma unroll
    for (int c = 0; c < 4; c++) v[c] = *(const float4*)(x + i + c * 4);
    const float* vv = (const float*)v;
    __nv_bfloat162 hp[8], lp[8];
#pragma unroll
    for (int j = 0; j < 8; j++) {
        bf16 h0 = __float2bfloat16_rn(vv[2*j]);
        bf16 h1 = __float2bfloat16_rn(vv[2*j+1]);
        hp[j] = __nv_bfloat162(h0, h1);
        lp[j] = __nv_bfloat162(__float2bfloat16_rn(vv[2*j]   - __bfloat162float(h0)),
                               __float2bfloat16_rn(vv[2*j+1] - __bfloat162float(h1)));
    }
    *(uint4*)(hi + i)     = ((uint4*)hp)[0];
    *(uint4*)(hi + i + 8) = ((uint4*)hp)[1];
    *(uint4*)(lo + i)     = ((uint4*)lp)[0];
    *(uint4*)(lo + i + 8) = ((uint4*)lp)[1];
}

__global__ void cvt16_k(const float* __restrict__ x, bf16* __restrict__ y, int n) {
    int i = (blockIdx.x * blockDim.x + threadIdx.x) * 16;
    if (i >= n) return;
    float4 v[4];
#pragma unroll
    for (int c = 0; c < 4; c++) v[c] = *(const float4*)(x + i + c * 4);
    const float* vv = (const float*)v;
    __nv_bfloat162 p[8];
#pragma unroll
    for (int j = 0; j < 8; j++)
        p[j] = __nv_bfloat162(__float2bfloat16_rn(vv[2*j]), __float2bfloat16_rn(vv[2*j+1]));
    *(uint4*)(y + i)     = ((uint4*)p)[0];
    *(uint4*)(y + i + 8) = ((uint4*)p)[1];
}

// ---------------- HMMA GEMM: C[i,n] = act(sum_k A[i,k]*W[n,k] + b[n]) ----
// SPLIT: 3-pass hi/lo bf16 (near-fp32).
// GROUPED: 0 = plain rows, 1 = per-expert rows (g_rows/g_cnt, blockIdx.z),
//          2 = flagged rows (g_flag/g_nflag).
// Tiles: CTA 128x128xK64, 8 warps of 64x32, cp.async double buffer,
// xor-swizzled smem, ldmatrix fragments.  (Proven R3 configuration.)
template <int SPLIT, int GROUPED, int RELU, typename OutT>
__global__ __launch_bounds__(NTH)
void gemm_mma(const bf16* __restrict__ Ahi, const bf16* __restrict__ Alo,
              const bf16* __restrict__ Whi, const bf16* __restrict__ Wlo,
              const float* __restrict__ bias, OutT* __restrict__ C,
              int N, int K, int plain_rows)
{
    int e = (GROUPED == 1) ? blockIdx.z : 0;
    int nrows = (GROUPED == 1) ? g_cnt[e] : (GROUPED == 2) ? g_nflag : plain_rows;
    int row0 = blockIdx.x * BM;
    if (row0 >= nrows) return;
    int col0 = blockIdx.y * BN;

    const bf16*  Wh = Whi + ((GROUPED == 1) ? (size_t)e * N * K : 0);
    const bf16*  Wl = Wlo + ((GROUPED == 1) ? (size_t)e * N * K : 0);
    const float* bp = bias + ((GROUPED == 1) ? (size_t)e * N : 0);

    extern __shared__ char smem[];
    int*   srow  = (int*)smem;            // [128]
    float* sbias = (float*)(smem + 512);  // [128]
    constexpr int HDR   = 1024;
    constexpr int TILE  = BM * 128;       // 16KB per operand tile
    constexpr int STAGE = (1 + SPLIT) * 2 * TILE;
    constexpr int AHI = 0, ALO = TILE, WHI = (1 + SPLIT) * TILE, WLO = WHI + TILE;

    int t = threadIdx.x;
    if (t < BM) {
        int gr = row0 + t;
        int cr = gr < nrows ? gr : nrows - 1;
        srow[t] = (GROUPED == 1) ? g_rows[e * B_ + cr]
                : (GROUPED == 2) ? g_flag[cr] : cr;
    }
    if (t < BN) sbias[t] = bp[col0 + t];
    __syncthreads();

    uint32_t sb = smem_u32(smem) + HDR;

    // loader: thread t -> row t>>1, 16B-chunks (t&1)*4 .. +3 (of 8 per 128B row)
    const int lrow = t >> 1, lhalf = (t & 1) * 4, lx7 = lrow & 7;
    const int nc = K >> 6;
    const size_t arow = (size_t)srow[lrow] * K;
    const size_t wrow = (size_t)(col0 + lrow) * K;

    auto issue = [&](int c) {
        uint32_t st = sb + (c & 1) * STAGE;
        size_t koff = (size_t)c * 64 + lhalf * 8;
#pragma unroll
        for (int j = 0; j < 4; j++) {
            uint32_t doff = lrow * 128 + (((lhalf + j) ^ lx7) * 16);
            cp16(st + AHI + doff, Ahi + arow + koff + j * 8);
            cp16(st + WHI + doff, Wh  + wrow + koff + j * 8);
            if (SPLIT) {
                cp16(st + ALO + doff, Alo + arow + koff + j * 8);
                cp16(st + WLO + doff, Wl  + wrow + koff + j * 8);
            }
        }
        cp_commit();
    };

    issue(0);
    issue(1);
    cp_wait<1>();
    __syncthreads();

    const int wid = t >> 5, lane = t & 31;
    const int wm = (wid & 1) * 64;   // warp row offset
    const int wn = (wid >> 1) * 32;  // warp col offset
    const int rb = lane & 15, csel = lane >> 4, x7 = rb & 7;

    float acc[4][4][4];
#pragma unroll
    for (int i = 0; i < 4; i++)
#pragma unroll
        for (int j = 0; j < 4; j++)
#pragma unroll
            for (int q = 0; q < 4; q++) acc[i][j][q] = 0.0f;

    uint32_t arow_b[4], wrow_b[2];
#pragma unroll
    for (int mi = 0; mi < 4; mi++) arow_b[mi] = (wm + mi * 16 + rb) * 128;
#pragma unroll
    for (int nb = 0; nb < 2; nb++) wrow_b[nb] = (wn + nb * 16 + rb) * 128;

    for (int c = 0; c < nc; c++) {
        uint32_t st = sb + (c & 1) * STAGE;
#pragma unroll
        for (int ks = 0; ks < 4; ks++) {
            uint32_t ksel = ((2 * ks + csel) ^ x7) * 16;
            uint32_t ah[4][4], bh[4][2];
#pragma unroll
            for (int mi = 0; mi < 4; mi++)
                ldmx4(ah[mi], st + AHI + arow_b[mi] + ksel);
#pragma unroll
            for (int nb = 0; nb < 2; nb++) {
                uint32_t r[4];
                ldmx4(r, st + WHI + wrow_b[nb] + ksel);
                bh[2 * nb][0] = r[0]; bh[2 * nb + 1][0] = r[1];
                bh[2 * nb][1] = r[2]; bh[2 * nb + 1][1] = r[3];
            }
#pragma unroll
            for (int mi = 0; mi < 4; mi++)
#pragma unroll
                for (int ni = 0; ni < 4; ni++)
                    mma16816(acc[mi][ni], ah[mi], bh[ni]);
            if (SPLIT) {
                uint32_t al[4][4], bl[4][2];
#pragma unroll
                for (int mi = 0; mi < 4; mi++)
                    ldmx4(al[mi], st + ALO + arow_b[mi] + ksel);
#pragma unroll
                for (int nb = 0; nb < 2; nb++) {
                    uint32_t r[4];
                    ldmx4(r, st + WLO + wrow_b[nb] + ksel);
                    bl[2 * nb][0] = r[0]; bl[2 * nb + 1][0] = r[1];
                    bl[2 * nb][1] = r[2]; bl[2 * nb + 1][1] = r[3];
                }
#pragma unroll
                for (int mi = 0; mi < 4; mi++)
#pragma unroll
                    for (int ni = 0; ni < 4; ni++) {
                        mma16816(acc[mi][ni], ah[mi], bl[ni]);
                        mma16816(acc[mi][ni], al[mi], bh[ni]);
                    }
            }
        }
        __syncthreads();
        if (c + 2 < nc) issue(c + 2);
        else            cp_commit();
        cp_wait<1>();
        __syncthreads();
    }

    // epilogue
    const int lr4 = lane >> 2, lc2 = 2 * (lane & 3);
#pragma unroll
    for (int mi = 0; mi < 4; mi++) {
        int r0i = wm + mi * 16 + lr4;
        int r1i = r0i + 8;
        bool v0 = (row0 + r0i) < nrows;
        bool v1 = (row0 + r1i) < nrows;
        size_t g0 = (size_t)srow[r0i] * N + col0;
        size_t g1 = (size_t)srow[r1i] * N + col0;
#pragma unroll
        for (int ni = 0; ni < 4; ni++) {
            int cc = wn + ni * 8 + lc2;
            float ba = sbias[cc], bb = sbias[cc + 1];
            float x0 = acc[mi][ni][0] + ba, x1 = acc[mi][ni][1] + bb;
            float y0 = acc[mi][ni][2] + ba, y1 = acc[mi][ni][3] + bb;
            if (RELU) {
                x0 = fmaxf(x0, 0.0f); x1 = fmaxf(x1, 0.0f);
                y0 = fmaxf(y0, 0.0f); y1 = fmaxf(y1, 0.0f);
            }
            if (sizeof(OutT) == 4) {
                if (v0) *(float2*)((float*)C + g0 + cc) = make_float2(x0, x1);
                if (v1) *(float2*)((float*)C + g1 + cc) = make_float2(y0, y1);
            } else {
                uint32_t p0, p1;
                asm("cvt.rn.bf16x2.f32 %0, %1, %2;" : "=r"(p0) : "f"(x1), "f"(x0));
                asm("cvt.rn.bf16x2.f32 %0, %1, %2;" : "=r"(p1) : "f"(y1), "f"(y0));
                if (v0) *(uint32_t*)((bf16*)C + g0 + cc) = p0;
                if (v1) *(uint32_t*)((bf16*)C + g1 + cc) = p1;
            }
        }
    }
}

// --------- logits + argmax with margin flagging -------------------------
__global__ void logits_argmax_kernel(const float* __restrict__ W3,
                                     const float* __restrict__ b3)
{
    __shared__ float sW[M_ * HH_];
    __shared__ float sb[M_];
    for (int i = threadIdx.x; i < M_ * HH_; i += blockDim.x) sW[i] = W3[i];
    if (threadIdx.x < M_) sb[threadIdx.x] = b3[threadIdx.x];
    __syncthreads();

    int gw   = (blockIdx.x * blockDim.x + threadIdx.x) >> 5;
    int lane = threadIdx.x & 31;
    int nw   = (gridDim.x * blockDim.x) >> 5;

    for (int row = gw; row < B_; row += nw) {
        const float* x = g_X1 + (size_t)row * HH_;
        float xv[16];
#pragma unroll
        for (int tt = 0; tt < 16; tt++) xv[tt] = x[lane + 32 * tt];
        float best = -3.0e38f, second = -3.0e38f;
        int   bi   = 0;
#pragma unroll
        for (int m = 0; m < M_; m++) {
            float p = 0.0f;
            const float* wrow = sW + m * HH_;
#pragma unroll
            for (int tt = 0; tt < 16; tt++)
                p = fmaf(xv[tt], wrow[lane + 32 * tt], p);
#pragma unroll
            for (int o = 16; o; o >>= 1) p += __shfl_xor_sync(0xffffffffu, p, o);
            p += sb[m];
            if (p > best) { second = best; best = p; bi = m; }
            else if (p > second) second = p;
        }
        if (lane == 0) {
            g_top[row] = bi;
            if (best - second < MARGIN_THRESH) {
                int fp = atomicAdd(&g_nflag, 1);
                g_flag[fp] = row;
            }
        }
    }
}

// --------- fix argmax for flagged rows (their X1 is now exact) ----------
__global__ void logits_fix_kernel(const float* __restrict__ W3,
                                  const float* __restrict__ b3)
{
    __shared__ float sW[M_ * HH_];
    __shared__ float sb[M_];
    for (int i = threadIdx.x; i < M_ * HH_; i += blockDim.x) sW[i] = W3[i];
    if (threadIdx.x < M_) sb[threadIdx.x] = b3[threadIdx.x];
    __syncthreads();

    int gw   = (blockIdx.x * blockDim.x + threadIdx.x) >> 5;
    int lane = threadIdx.x & 31;
    int nw   = (gridDim.x * blockDim.x) >> 5;
    int nf   = g_nflag;

    for (int idx = gw; idx < nf; idx += nw) {
        int row = g_flag[idx];
        const float* x = g_X1 + (size_t)row * HH_;
        float xv[16];
#pragma unroll
        for (int tt = 0; tt < 16; tt++) xv[tt] = x[lane + 32 * tt];
        float best = -3.0e38f;
        int   bi   = 0;
#pragma unroll
        for (int m = 0; m < M_; m++) {
            float p = 0.0f;
            const float* wrow = sW + m * HH_;
#pragma unroll
            for (int tt = 0; tt < 16; tt++)
                p = fmaf(xv[tt], wrow[lane + 32 * tt], p);
#pragma unroll
            for (int o = 16; o; o >>= 1) p += __shfl_xor_sync(0xffffffffu, p, o);
            p += sb[m];
            if (p > best) { best = p; bi = m; }
        }
        if (lane == 0) g_top[row] = bi;
    }
}

__global__ void zero_kernel() {
    if (threadIdx.x < M_) g_cnt[threadIdx.x] = 0;
    if (threadIdx.x == M_) g_nflag = 0;
}

__global__ void scatter_kernel() {
    int b = blockIdx.x * blockDim.x + threadIdx.x;
    if (b < B_) {
        int m = g_top[b];
        int p = atomicAdd(&g_cnt[m], 1);
        g_rows[m * B_ + p] = b;
    }
}

// normalize(g*v) == v / max(||v||,eps) for gate g > 0 (top-1 prob >= 1/16)
__global__ void finalize_kernel(const float* __restrict__ Q, float* __restrict__ out)
{
    int row = blockIdx.x;
    const float* o = g_Obuf + (size_t)row * H_;
    float s = 0.0f;
    for (int i = threadIdx.x; i < H_; i += 256) { float v = o[i]; s = fmaf(v, v, s); }
#pragma unroll
    for (int off = 16; off; off >>= 1) s += __shfl_xor_sync(0xffffffffu, s, off);
    __shared__ float red[8];
    if ((threadIdx.x & 31) == 0) red[threadIdx.x >> 5] = s;
    __syncthreads();
    float tot = 0.0f;
#pragma unroll
    for (int w = 0; w < 8; w++) tot += red[w];
    float inv = 1.0f / fmaxf(sqrtf(tot), 1e-6f);

    const float* qr = Q + (size_t)row * H_;
    float* orow = out + (size_t)row * H_;
    for (int i = threadIdx.x; i < H_; i += 256)
        orow[i] = fmaf(o[i], inv, qr[i]);
}

// ---------------- launch ----------------
extern "C" void kernel_launch(void* const* d_in, const int* in_sizes, int n_in,
                              void* d_out, int out_size)
{
    const float* q   = (const float*)d_in[0];
    const float* c1w = (const float*)d_in[1];
    const float* c1b = (const float*)d_in[2];
    const float* c3w = (const float*)d_in[3];
    const float* c3b = (const float*)d_in[4];
    const float* ew1 = (const float*)d_in[5];
    const float* eb1 = (const float*)d_in[6];
    const float* ew2 = (const float*)d_in[7];
    const float* eb2 = (const float*)d_in[8];
    float* out = (float*)d_out;

    void *pqh, *pql, *pw1h, *pw1l, *pe1, *pe2, *pX1, *pHb, *pO;
    cudaGetSymbolAddress(&pqh,  g_qhi);
    cudaGetSymbolAddress(&pql,  g_qlo);
    cudaGetSymbolAddress(&pw1h, g_w1hi);
    cudaGetSymbolAddress(&pw1l, g_w1lo);
    cudaGetSymbolAddress(&pe1,  g_ew1b);
    cudaGetSymbolAddress(&pe2,  g_ew2b);
    cudaGetSymbolAddress(&pX1,  g_X1);
    cudaGetSymbolAddress(&pHb,  g_Hb);
    cudaGetSymbolAddress(&pO,   g_Obuf);

    // conversions (q and w1 split hi/lo for the exact-fallback path)
    split16_k<<<B_ * H_ / 16 / 256, 256>>>(q, (bf16*)pqh, (bf16*)pql, B_ * H_);
    split16_k<<<HH_ * H_ / 16 / 256, 256>>>(c1w, (bf16*)pw1h, (bf16*)pw1l, HH_ * H_);
    cvt16_k<<<M_ * HH_ * H_ / 16 / 256, 256>>>(ew1, (bf16*)pe1, M_ * HH_ * H_);
    cvt16_k<<<M_ * H_ * HH_ / 16 / 256, 256>>>(ew2, (bf16*)pe2, M_ * H_ * HH_);

    constexpr int SMEM_STD   = 1024 + 2 * 2 * BM * 128;  // 66560
    constexpr int SMEM_SPLIT = 1024 + 2 * 4 * BM * 128;  // 132096

    cudaFuncSetAttribute(gemm_mma<0, 0, 1, float>,
                         cudaFuncAttributeMaxDynamicSharedMemorySize, SMEM_STD);
    cudaFuncSetAttribute(gemm_mma<1, 2, 1, float>,
                         cudaFuncAttributeMaxDynamicSharedMemorySize, SMEM_SPLIT);
    cudaFuncSetAttribute(gemm_mma<0, 1, 1, bf16>,
                         cudaFuncAttributeMaxDynamicSharedMemorySize, SMEM_STD);
    cudaFuncSetAttribute(gemm_mma<0, 1, 0, float>,
                         cudaFuncAttributeMaxDynamicSharedMemorySize, SMEM_STD);

    // 1) gating hidden, single-pass bf16: X1 = relu(Q @ c1w^T + b)
    gemm_mma<0, 0, 1, float><<<dim3(B_ / BM, HH_ / BN, 1), NTH, SMEM_STD>>>(
        (const bf16*)pqh, nullptr, (const bf16*)pw1h, nullptr,
        c1b, (float*)pX1, HH_, H_, B_);

    // 2) zero counters, then logits + argmax with margin flagging
    zero_kernel<<<1, 32>>>();
    logits_argmax_kernel<<<64, 256>>>(c3w, c3b);

    // 3) exact (split 3-pass) X1 recompute for flagged rows only
    gemm_mma<1, 2, 1, float><<<dim3(B_ / BM, HH_ / BN, 1), NTH, SMEM_SPLIT>>>(
        (const bf16*)pqh, (const bf16*)pql, (const bf16*)pw1h, (const bf16*)pw1l,
        c1b, (float*)pX1, HH_, H_, 0);
    logits_fix_kernel<<<32, 256>>>(c3w, c3b);

    // 4) bucket rows by expert
    scatter_kernel<<<B_ / 256, 256>>>();

    // 5) expert hidden: H = relu(Qg @ ew1[m]^T + b1[m])  (bf16 out)
    gemm_mma<0, 1, 1, bf16><<<dim3(B_ / BM, HH_ / BN, M_), NTH, SMEM_STD>>>(
        (const bf16*)pqh, nullptr, (const bf16*)pe1, nullptr,
        eb1, (bf16*)pHb, HH_, H_, 0);

    // 6) expert out: O = Hg @ ew2[m]^T + b2[m]  (fp32 out)
    gemm_mma<0, 1, 0, float><<<dim3(B_ / BM, H_ / BN, M_), NTH, SMEM_STD>>>(
        (const bf16*)pHb, nullptr, (const bf16*)pe2, nullptr,
        eb2, (float*)pO, H_, HH_, 0);

    // 7) out = normalize(O) + Q
    finalize_kernel<<<B_, 256>>>(q, out);
}

// round 6
// speedup vs baseline: 1.1986x; 1.0066x over previous
#include <cuda_runtime.h>
#include <cuda_bf16.h>
#include <cstdint>
#include <math.h>

#define B_  8192
#define H_  1024
#define HH_ 512
#define M_  16
#define BM  128
#define BN  128
#define NTH 256
#define MARGIN_THRESH 0.03f

typedef __nv_bfloat16 bf16;

// ---------------- scratch (device globals, no allocation) ----------------
__device__ bf16  g_qhi[B_ * H_];
__device__ bf16  g_qlo[B_ * H_];
__device__ bf16  g_w1hi[HH_ * H_];
__device__ bf16  g_w1lo[HH_ * H_];
__device__ bf16  g_ew1b[M_ * HH_ * H_];
__device__ bf16  g_ew2b[M_ * H_ * HH_];
__device__ float g_X1[B_ * HH_];
__device__ bf16  g_Hb[B_ * HH_];
__device__ float g_Obuf[B_ * H_];
__device__ int   g_top[B_];
__device__ int   g_rows[M_ * B_];
__device__ int   g_cnt[M_];
__device__ int   g_flag[B_];
__device__ int   g_nflag;

// ---------------- PTX helpers (all sm_80-compatible) ----------------
__device__ __forceinline__ uint32_t smem_u32(const void* p) {
    uint32_t a;
    asm("{ .reg .u64 t; cvta.to.shared.u64 t, %1; cvt.u32.u64 %0, t; }" : "=r"(a) : "l"(p));
    return a;
}
__device__ __forceinline__ void cp16(uint32_t dst, const void* src) {
    asm volatile("cp.async.cg.shared.global [%0], [%1], 16;" :: "r"(dst), "l"(src));
}
__device__ __forceinline__ void cp_commit() { asm volatile("cp.async.commit_group;" ::: "memory"); }
template <int N> __device__ __forceinline__ void cp_wait() {
    asm volatile("cp.async.wait_group %0;" :: "n"(N) : "memory");
}
__device__ __forceinline__ void ldmx4(uint32_t* r, uint32_t addr) {
    asm volatile("ldmatrix.sync.aligned.m8n8.x4.shared.b16 {%0,%1,%2,%3}, [%4];"
                 : "=r"(r[0]), "=r"(r[1]), "=r"(r[2]), "=r"(r[3]) : "r"(addr));
}
__device__ __forceinline__ void mma16816(float* d, const uint32_t* a, const uint32_t* b) {
    asm volatile(
        "mma.sync.aligned.m16n8k16.row.col.f32.bf16.bf16.f32 "
        "{%0,%1,%2,%3}, {%4,%5,%6,%7}, {%8,%9}, {%0,%1,%2,%3};"
        : "+f"(d[0]), "+f"(d[1]), "+f"(d[2]), "+f"(d[3])
        : "r"(a[0]), "r"(a[1]), "r"(a[2]), "r"(a[3]), "r"(b[0]), "r"(b[1]));
}

// ---------------- conversion kernels (16 elems / thread) -------
__global__ void split16_k(const float* __restrict__ x, bf16* __restrict__ hi,
                          bf16* __restrict__ lo, int n) {
    int i = (blockIdx.x * blockDim.x + threadIdx.x) * 16;
    if (i >= n) return;
    float4 v[4];
#pragma unroll
    for (int c = 0; c < 4; c++) v[c] = *(const float4*)(x + i + c * 4);
    const float* vv = (const float*)v;
    __nv_bfloat162 hp[8], lp[8];
#pragma unroll
    for (int j = 0; j < 8; j++) {
        bf16 h0 = __float2bfloat16_rn(vv[2*j]);
        bf16 h1 = __float2bfloat16_rn(vv[2*j+1]);
        hp[j] = __nv_bfloat162(h0, h1);
        lp[j] = __nv_bfloat162(__float2bfloat16_rn(vv[2*j]   - __bfloat162float(h0)),
                               __float2bfloat16_rn(vv[2*j+1] - __bfloat162float(h1)));
    }
    *(uint4*)(hi + i)     = ((uint4*)hp)[0];
    *(uint4*)(hi + i + 8) = ((uint4*)hp)[1];
    *(uint4*)(lo + i)     = ((uint4*)lp)[0];
    *(uint4*)(lo + i + 8) = ((uint4*)lp)[1];
}

__global__ void cvt16_k(const float* __restrict__ x, bf16* __restrict__ y, int n) {
    int i = (blockIdx.x * blockDim.x + threadIdx.x) * 16;
    if (i >= n) return;
    float4 v[4];
#pragma unroll
    for (int c = 0; c < 4; c++) v[c] = *(const float4*)(x + i + c * 4);
    const float* vv = (const float*)v;
    __nv_bfloat162 p[8];
#pragma unroll
    for (int j = 0; j < 8; j++)
        p[j] = __nv_bfloat162(__float2bfloat16_rn(vv[2*j]), __float2bfloat16_rn(vv[2*j+1]));
    *(uint4*)(y + i)     = ((uint4*)p)[0];
    *(uint4*)(y + i + 8) = ((uint4*)p)[1];
}

// ---------------- HMMA GEMM: C[i,n] = act(sum_k A[i,k]*W[n,k] + b[n]) ----
// SPLIT=0: 4-stage cp.async pipeline + register fragment double-buffering,
//          ONE barrier per K-chunk.
// SPLIT=1: 3-pass hi/lo bf16 (near-fp32), proven 2-stage loop (rarely hot).
// GROUPED: 0 = plain rows, 1 = per-expert (g_rows/g_cnt, blockIdx.z),
//          2 = flagged rows (g_flag/g_nflag).
template <int SPLIT, int GROUPED, int RELU, typename OutT>
__global__ __launch_bounds__(NTH)
void gemm_mma(const bf16* __restrict__ Ahi, const bf16* __restrict__ Alo,
              const bf16* __restrict__ Whi, const bf16* __restrict__ Wlo,
              const float* __restrict__ bias, OutT* __restrict__ C,
              int N, int K, int plain_rows)
{
    int e = (GROUPED == 1) ? blockIdx.z : 0;
    int nrows = (GROUPED == 1) ? g_cnt[e] : (GROUPED == 2) ? g_nflag : plain_rows;
    int row0 = blockIdx.x * BM;
    if (row0 >= nrows) return;
    int col0 = blockIdx.y * BN;

    const bf16*  Wh = Whi + ((GROUPED == 1) ? (size_t)e * N * K : 0);
    const bf16*  Wl = Wlo + ((GROUPED == 1) ? (size_t)e * N * K : 0);
    const float* bp = bias + ((GROUPED == 1) ? (size_t)e * N : 0);

    extern __shared__ char smem[];
    int*   srow  = (int*)smem;            // [128]
    float* sbias = (float*)(smem + 512);  // [128]
    constexpr int HDR  = 1024;
    constexpr int TILE = BM * 128;        // 16KB per operand tile

    int t = threadIdx.x;
    if (t < BM) {
        int gr = row0 + t;
        int cr = gr < nrows ? gr : nrows - 1;
        srow[t] = (GROUPED == 1) ? g_rows[e * B_ + cr]
                : (GROUPED == 2) ? g_flag[cr] : cr;
    }
    if (t < BN) sbias[t] = bp[col0 + t];
    __syncthreads();

    uint32_t sb = smem_u32(smem) + HDR;

    // loader: thread t -> row t>>1, 16B chunks (t&1)*4 .. +3
    const int lrow = t >> 1, lhalf = (t & 1) * 4, lx7 = lrow & 7;
    const int nc = K >> 6;
    const size_t arow = (size_t)srow[lrow] * K;
    const size_t wrow = (size_t)(col0 + lrow) * K;

    const int wid = t >> 5, lane = t & 31;
    const int wm = (wid & 1) * 64;   // warp row offset
    const int wn = (wid >> 1) * 32;  // warp col offset
    const int rb = lane & 15, csel = lane >> 4, x7 = rb & 7;

    float acc[4][4][4];
#pragma unroll
    for (int i = 0; i < 4; i++)
#pragma unroll
        for (int j = 0; j < 4; j++)
#pragma unroll
            for (int q = 0; q < 4; q++) acc[i][j][q] = 0.0f;

    uint32_t arow_b[4], wrow_b[2];
#pragma unroll
    for (int mi = 0; mi < 4; mi++) arow_b[mi] = (wm + mi * 16 + rb) * 128;
#pragma unroll
    for (int nb = 0; nb < 2; nb++) wrow_b[nb] = (wn + nb * 16 + rb) * 128;

    if constexpr (!SPLIT) {
        // ---------- fast path: 4-stage pipeline, frag double-buffer ----------
        auto stA = [&](int c) { return sb + (uint32_t)(c & 3) * (2 * TILE); };
        auto issueN = [&](int c) {
            uint32_t st = stA(c);
            size_t koff = (size_t)c * 64 + lhalf * 8;
#pragma unroll
            for (int j = 0; j < 4; j++) {
                uint32_t doff = lrow * 128 + (((lhalf + j) ^ lx7) * 16);
                cp16(st + doff, Ahi + arow + koff + j * 8);
                cp16(st + TILE + doff, Wh + wrow + koff + j * 8);
            }
            cp_commit();
        };

        uint32_t fa[2][4][4], fb[2][4][2];
        auto ldfrag = [&](int p, uint32_t st, int ks) {
            uint32_t ksel = (uint32_t)((2 * ks + csel) ^ x7) * 16;
#pragma unroll
            for (int mi = 0; mi < 4; mi++)
                ldmx4(fa[p][mi], st + arow_b[mi] + ksel);
#pragma unroll
            for (int nb = 0; nb < 2; nb++) {
                uint32_t r[4];
                ldmx4(r, st + TILE + wrow_b[nb] + ksel);
                fb[p][2 * nb][0] = r[0]; fb[p][2 * nb + 1][0] = r[1];
                fb[p][2 * nb][1] = r[2]; fb[p][2 * nb + 1][1] = r[3];
            }
        };

        issueN(0); issueN(1); issueN(2);
        cp_wait<1>();
        __syncthreads();
        ldfrag(0, stA(0), 0);

        for (int c = 0; c < nc; c++) {
            if (c + 3 < nc) issueN(c + 3);
            else            cp_commit();
            uint32_t stc = stA(c);
            uint32_t stn = stA(c + 1 < nc ? c + 1 : c);
#pragma unroll
            for (int ks = 0; ks < 4; ks++) {
                int pc = ks & 1, pn = pc ^ 1;
                ldfrag(pn, ks < 3 ? stc : stn, (ks + 1) & 3);
#pragma unroll
                for (int mi = 0; mi < 4; mi++)
#pragma unroll
                    for (int ni = 0; ni < 4; ni++)
                        mma16816(acc[mi][ni], fa[pc][mi], fb[pc][ni]);
            }
            cp_wait<1>();
            __syncthreads();
        }
    } else {
        // ---------- split path (rare): proven 2-stage loop ----------
        constexpr int STAGE = 4 * TILE;
        constexpr int AHI = 0, ALO = TILE, WHI = 2 * TILE, WLO = 3 * TILE;
        auto issue = [&](int c) {
            uint32_t st = sb + (c & 1) * STAGE;
            size_t koff = (size_t)c * 64 + lhalf * 8;
#pragma unroll
            for (int j = 0; j < 4; j++) {
                uint32_t doff = lrow * 128 + (((lhalf + j) ^ lx7) * 16);
                cp16(st + AHI + doff, Ahi + arow + koff + j * 8);
                cp16(st + WHI + doff, Wh  + wrow + koff + j * 8);
                cp16(st + ALO + doff, Alo + arow + koff + j * 8);
                cp16(st + WLO + doff, Wl  + wrow + koff + j * 8);
            }
            cp_commit();
        };

        issue(0); issue(1);
        cp_wait<1>();
        __syncthreads();

        for (int c = 0; c < nc; c++) {
            uint32_t st = sb + (c & 1) * STAGE;
#pragma unroll
            for (int ks = 0; ks < 4; ks++) {
                uint32_t ksel = (uint32_t)((2 * ks + csel) ^ x7) * 16;
                uint32_t ah[4][4], bh[4][2];
#pragma unroll
                for (int mi = 0; mi < 4; mi++)
                    ldmx4(ah[mi], st + AHI + arow_b[mi] + ksel);
#pragma unroll
                for (int nb = 0; nb < 2; nb++) {
                    uint32_t r[4];
                    ldmx4(r, st + WHI + wrow_b[nb] + ksel);
                    bh[2 * nb][0] = r[0]; bh[2 * nb + 1][0] = r[1];
                    bh[2 * nb][1] = r[2]; bh[2 * nb + 1][1] = r[3];
                }
#pragma unroll
                for (int mi = 0; mi < 4; mi++)
#pragma unroll
                    for (int ni = 0; ni < 4; ni++)
                        mma16816(acc[mi][ni], ah[mi], bh[ni]);
                uint32_t al[4][4], bl[4][2];
#pragma unroll
                for (int mi = 0; mi < 4; mi++)
                    ldmx4(al[mi], st + ALO + arow_b[mi] + ksel);
#pragma unroll
                for (int nb = 0; nb < 2; nb++) {
                    uint32_t r[4];
                    ldmx4(r, st + WLO + wrow_b[nb] + ksel);
                    bl[2 * nb][0] = r[0]; bl[2 * nb + 1][0] = r[1];
                    bl[2 * nb][1] = r[2]; bl[2 * nb + 1][1] = r[3];
                }
#pragma unroll
                for (int mi = 0; mi < 4; mi++)
#pragma unroll
                    for (int ni = 0; ni < 4; ni++) {
                        mma16816(acc[mi][ni], ah[mi], bl[ni]);
                        mma16816(acc[mi][ni], al[mi], bh[ni]);
                    }
            }
            __syncthreads();
            if (c + 2 < nc) issue(c + 2);
            else            cp_commit();
            cp_wait<1>();
            __syncthreads();
        }
    }

    // epilogue
    const int lr4 = lane >> 2, lc2 = 2 * (lane & 3);
#pragma unroll
    for (int mi = 0; mi < 4; mi++) {
        int r0i = wm + mi * 16 + lr4;
        int r1i = r0i + 8;
        bool v0 = (row0 + r0i) < nrows;
        bool v1 = (row0 + r1i) < nrows;
        size_t g0 = (size_t)srow[r0i] * N + col0;
        size_t g1 = (size_t)srow[r1i] * N + col0;
#pragma unroll
        for (int ni = 0; ni < 4; ni++) {
            int cc = wn + ni * 8 + lc2;
            float ba = sbias[cc], bb = sbias[cc + 1];
            float x0 = acc[mi][ni][0] + ba, x1 = acc[mi][ni][1] + bb;
            float y0 = acc[mi][ni][2] + ba, y1 = acc[mi][ni][3] + bb;
            if (RELU) {
                x0 = fmaxf(x0, 0.0f); x1 = fmaxf(x1, 0.0f);
                y0 = fmaxf(y0, 0.0f); y1 = fmaxf(y1, 0.0f);
            }
            if (sizeof(OutT) == 4) {
                if (v0) *(float2*)((float*)C + g0 + cc) = make_float2(x0, x1);
                if (v1) *(float2*)((float*)C + g1 + cc) = make_float2(y0, y1);
            } else {
                uint32_t p0, p1;
                asm("cvt.rn.bf16x2.f32 %0, %1, %2;" : "=r"(p0) : "f"(x1), "f"(x0));
                asm("cvt.rn.bf16x2.f32 %0, %1, %2;" : "=r"(p1) : "f"(y1), "f"(y0));
                if (v0) *(uint32_t*)((bf16*)C + g0 + cc) = p0;
                if (v1) *(uint32_t*)((bf16*)C + g1 + cc) = p1;
            }
        }
    }
}

// --------- logits + argmax with margin flagging -------------------------
__global__ void logits_argmax_kernel(const float* __restrict__ W3,
                                     const float* __restrict__ b3)
{
    __shared__ float sW[M_ * HH_];
    __shared__ float sb[M_];
    for (int i = threadIdx.x; i < M_ * HH_; i += blockDim.x) sW[i] = W3[i];
    if (threadIdx.x < M_) sb[threadIdx.x] = b3[threadIdx.x];
    __syncthreads();

    int gw   = (blockIdx.x * blockDim.x + threadIdx.x) >> 5;
    int lane = threadIdx.x & 31;
    int nw   = (gridDim.x * blockDim.x) >> 5;

    for (int row = gw; row < B_; row += nw) {
        const float* x = g_X1 + (size_t)row * HH_;
        float xv[16];
#pragma unroll
        for (int tt = 0; tt < 16; tt++) xv[tt] = x[lane + 32 * tt];
        float best = -3.0e38f, second = -3.0e38f;
        int   bi   = 0;
#pragma unroll
        for (int m = 0; m < M_; m++) {
            float p = 0.0f;
            const float* wrow = sW + m * HH_;
#pragma unroll
            for (int tt = 0; tt < 16; tt++)
                p = fmaf(xv[tt], wrow[lane + 32 * tt], p);
#pragma unroll
            for (int o = 16; o; o >>= 1) p += __shfl_xor_sync(0xffffffffu, p, o);
            p += sb[m];
            if (p > best) { second = best; best = p; bi = m; }
            else if (p > second) second = p;
        }
        if (lane == 0) {
            g_top[row] = bi;
            if (best - second < MARGIN_THRESH) {
                int fp = atomicAdd(&g_nflag, 1);
                g_flag[fp] = row;
            }
        }
    }
}

// --------- fix argmax for flagged rows (their X1 is now exact) ----------
__global__ void logits_fix_kernel(const float* __restrict__ W3,
                                  const float* __restrict__ b3)
{
    __shared__ float sW[M_ * HH_];
    __shared__ float sb[M_];
    for (int i = threadIdx.x; i < M_ * HH_; i += blockDim.x) sW[i] = W3[i];
    if (threadIdx.x < M_) sb[threadIdx.x] = b3[threadIdx.x];
    __syncthreads();

    int gw   = (blockIdx.x * blockDim.x + threadIdx.x) >> 5;
    int lane = threadIdx.x & 31;
    int nw   = (gridDim.x * blockDim.x) >> 5;
    int nf   = g_nflag;

    for (int idx = gw; idx < nf; idx += nw) {
        int row = g_flag[idx];
        const float* x = g_X1 + (size_t)row * HH_;
        float xv[16];
#pragma unroll
        for (int tt = 0; tt < 16; tt++) xv[tt] = x[lane + 32 * tt];
        float best = -3.0e38f;
        int   bi   = 0;
#pragma unroll
        for (int m = 0; m < M_; m++) {
            float p = 0.0f;
            const float* wrow = sW + m * HH_;
#pragma unroll
            for (int tt = 0; tt < 16; tt++)
                p = fmaf(xv[tt], wrow[lane + 32 * tt], p);
#pragma unroll
            for (int o = 16; o; o >>= 1) p += __shfl_xor_sync(0xffffffffu, p, o);
            p += sb[m];
            if (p > best) { best = p; bi = m; }
        }
        if (lane == 0) g_top[row] = bi;
    }
}

__global__ void zero_kernel() {
    if (threadIdx.x < M_) g_cnt[threadIdx.x] = 0;
    if (threadIdx.x == M_) g_nflag = 0;
}

__global__ void scatter_kernel() {
    int b = blockIdx.x * blockDim.x + threadIdx.x;
    if (b < B_) {
        int m = g_top[b];
        int p = atomicAdd(&g_cnt[m], 1);
        g_rows[m * B_ + p] = b;
    }
}

// normalize(g*v) == v / max(||v||,eps) for gate g > 0 (top-1 prob >= 1/16)
__global__ void finalize_kernel(const float* __restrict__ Q, float* __restrict__ out)
{
    int row = blockIdx.x;
    const float* o = g_Obuf + (size_t)row * H_;
    float s = 0.0f;
    for (int i = threadIdx.x; i < H_; i += 256) { float v = o[i]; s = fmaf(v, v, s); }
#pragma unroll
    for (int off = 16; off; off >>= 1) s += __shfl_xor_sync(0xffffffffu, s, off);
    __shared__ float red[8];
    if ((threadIdx.x & 31) == 0) red[threadIdx.x >> 5] = s;
    __syncthreads();
    float tot = 0.0f;
#pragma unroll
    for (int w = 0; w < 8; w++) tot += red[w];
    float inv = 1.0f / fmaxf(sqrtf(tot), 1e-6f);

    const float* qr = Q + (size_t)row * H_;
    float* orow = out + (size_t)row * H_;
    for (int i = threadIdx.x; i < H_; i += 256)
        orow[i] = fmaf(o[i], inv, qr[i]);
}

// ---------------- launch ----------------
extern "C" void kernel_launch(void* const* d_in, const int* in_sizes, int n_in,
                              void* d_out, int out_size)
{
    const float* q   = (const float*)d_in[0];
    const float* c1w = (const float*)d_in[1];
    const float* c1b = (const float*)d_in[2];
    const float* c3w = (const float*)d_in[3];
    const float* c3b = (const float*)d_in[4];
    const float* ew1 = (const float*)d_in[5];
    const float* eb1 = (const float*)d_in[6];
    const float* ew2 = (const float*)d_in[7];
    const float* eb2 = (const float*)d_in[8];
    float* out = (float*)d_out;

    void *pqh, *pql, *pw1h, *pw1l, *pe1, *pe2, *pX1, *pHb, *pO;
    cudaGetSymbolAddress(&pqh,  g_qhi);
    cudaGetSymbolAddress(&pql,  g_qlo);
    cudaGetSymbolAddress(&pw1h, g_w1hi);
    cudaGetSymbolAddress(&pw1l, g_w1lo);
    cudaGetSymbolAddress(&pe1,  g_ew1b);
    cudaGetSymbolAddress(&pe2,  g_ew2b);
    cudaGetSymbolAddress(&pX1,  g_X1);
    cudaGetSymbolAddress(&pHb,  g_Hb);
    cudaGetSymbolAddress(&pO,   g_Obuf);

    // conversions (q and w1 split hi/lo for the exact-fallback path)
    split16_k<<<B_ * H_ / 16 / 256, 256>>>(q, (bf16*)pqh, (bf16*)pql, B_ * H_);
    split16_k<<<HH_ * H_ / 16 / 256, 256>>>(c1w, (bf16*)pw1h, (bf16*)pw1l, HH_ * H_);
    cvt16_k<<<M_ * HH_ * H_ / 16 / 256, 256>>>(ew1, (bf16*)pe1, M_ * HH_ * H_);
    cvt16_k<<<M_ * H_ * HH_ / 16 / 256, 256>>>(ew2, (bf16*)pe2, M_ * H_ * HH_);

    // both paths use: 1024 hdr + 128KB tiles (4 stages x 32KB  |  2 stages x 64KB)
    constexpr int SMEM = 1024 + 8 * BM * 128;  // 132096

    cudaFuncSetAttribute(gemm_mma<0, 0, 1, float>,
                         cudaFuncAttributeMaxDynamicSharedMemorySize, SMEM);
    cudaFuncSetAttribute(gemm_mma<1, 2, 1, float>,
                         cudaFuncAttributeMaxDynamicSharedMemorySize, SMEM);
    cudaFuncSetAttribute(gemm_mma<0, 1, 1, bf16>,
                         cudaFuncAttributeMaxDynamicSharedMemorySize, SMEM);
    cudaFuncSetAttribute(gemm_mma<0, 1, 0, float>,
                         cudaFuncAttributeMaxDynamicSharedMemorySize, SMEM);

    // 1) gating hidden, single-pass bf16: X1 = relu(Q @ c1w^T + b)
    gemm_mma<0, 0, 1, float><<<dim3(B_ / BM, HH_ / BN, 1), NTH, SMEM>>>(
        (const bf16*)pqh, nullptr, (const bf16*)pw1h, nullptr,
        c1b, (float*)pX1, HH_, H_, B_);

    // 2) zero counters, then logits + argmax with margin flagging
    zero_kernel<<<1, 32>>>();
    logits_argmax_kernel<<<64, 256>>>(c3w, c3b);

    // 3) exact (split 3-pass) X1 recompute for flagged rows only
    gemm_mma<1, 2, 1, float><<<dim3(B_ / BM, HH_ / BN, 1), NTH, SMEM>>>(
        (const bf16*)pqh, (const bf16*)pql, (const bf16*)pw1h, (const bf16*)pw1l,
        c1b, (float*)pX1, HH_, H_, 0);
    logits_fix_kernel<<<32, 256>>>(c3w, c3b);

    // 4) bucket rows by expert
    scatter_kernel<<<B_ / 256, 256>>>();

    // 5) expert hidden: H = relu(Qg @ ew1[m]^T + b1[m])  (bf16 out)
    gemm_mma<0, 1, 1, bf16><<<dim3(B_ / BM, HH_ / BN, M_), NTH, SMEM>>>(
        (const bf16*)pqh, nullptr, (const bf16*)pe1, nullptr,
        eb1, (bf16*)pHb, HH_, H_, 0);

    // 6) expert out: O = Hg @ ew2[m]^T + b2[m]  (fp32 out)
    gemm_mma<0, 1, 0, float><<<dim3(B_ / BM, H_ / BN, M_), NTH, SMEM>>>(
        (const bf16*)pHb, nullptr, (const bf16*)pe2, nullptr,
        eb2, (float*)pO, H_, HH_, 0);

    // 7) out = normalize(O) + Q
    finalize_kernel<<<B_, 256>>>(q, out);
}